// round 16
// baseline (speedup 1.0000x reference)
#include <cuda_runtime.h>
#include <cuda.h>
#include <cuda_bf16.h>
#include <math.h>
#include <stdint.h>
#include <dlfcn.h>

#define V   50257
#define EMB 1024
#define HD  1024
#define HE  1024
#define L   128
#define B   64
#define CAT 2048
#define G3  3072

// ---------------- scratch ----------------------------------------------------
__device__ float         g_attn_in[B * CAT];
__device__ float         g_comb_in[B * CAT];
__device__ float         g_attn_logits[B * L];
__device__ float         g_x[B * HE];
__device__ float         g_gi[B * G3];
__device__ float         g_gh[B * G3];
__device__ float         g_logits[B * V];
__device__ __nv_bfloat16 g_h_bf16[B * HD];
#define NB_OUT 393
__device__ float         g_pmax[B * NB_OUT];
__device__ float         g_psum[B * NB_OUT];

// ---------------- fused embed + concat + bias/zero init ----------------------
#define SEG0 (B * L)
#define SEG1 (SEG0 + B * HE)
#define SEG2 (SEG1 + B * G3)
#define SEG3 (SEG2 + B * G3)
#define SEG4 (SEG3 + B * HE)
#define NBIAS ((SEG4 + 255) / 256)
__global__ void prep_kernel(const int* __restrict__ idx,
                            const float* __restrict__ hidden,
                            const float* __restrict__ emb_table,
                            const float* __restrict__ attn_b,
                            const float* __restrict__ comb_b,
                            const float* __restrict__ b_ih,
                            const float* __restrict__ b_hh) {
    int blk = blockIdx.x;
    if (blk < B) {
        int b = blk;
        int row = idx[b];
        for (int k = threadIdx.x; k < EMB; k += 256) {
            float e = emb_table[(size_t)row * EMB + k];
            g_attn_in[b * CAT + k] = e;
            g_comb_in[b * CAT + k] = e;
            g_attn_in[b * CAT + EMB + k] = hidden[b * HD + k];
        }
    } else {
        int i = (blk - B) * 256 + threadIdx.x;
        if (i < SEG0) {
            g_attn_logits[i] = attn_b[i & (L - 1)];
        } else if (i < SEG1) {
            int j = i - SEG0; g_x[j] = comb_b[j & (HE - 1)];
        } else if (i < SEG2) {
            int j = i - SEG1; g_gi[j] = b_ih[j % G3];
        } else if (i < SEG3) {
            int j = i - SEG2; g_gh[j] = b_hh[j % G3];
        } else if (i < SEG4) {
            int j = i - SEG3;
            int b = j / HE, e = j % HE;
            g_comb_in[b * CAT + EMB + e] = 0.0f;
        }
    }
}

// ---------------- helpers ----------------------------------------------------
__device__ __forceinline__ void cp16(void* saddr, const void* g, bool p) {
    uint32_t s = (uint32_t)__cvta_generic_to_shared(saddr);
    int sz = p ? 16 : 0;
    asm volatile("cp.async.cg.shared.global [%0], [%1], 16, %2;\n"
                 :: "r"(s), "l"(g), "r"(sz));
}
__device__ __forceinline__ unsigned packbf(float a, float b) {
    __nv_bfloat162 p = __float22bfloat162_rn(make_float2(a, b));
    return *reinterpret_cast<unsigned*>(&p);
}
__device__ __forceinline__ unsigned f2tf(float f) {
    unsigned u;
    asm("cvt.rna.tf32.f32 %0, %1;" : "=r"(u) : "f"(f));
    return u;
}
__device__ __forceinline__ uint32_t s2u32(const void* p) {
    return (uint32_t)__cvta_generic_to_shared(p);
}
__device__ __forceinline__ void mbar_init(uint32_t a, uint32_t cnt) {
    asm volatile("mbarrier.init.shared.b64 [%0], %1;" :: "r"(a), "r"(cnt) : "memory");
}
__device__ __forceinline__ void mbar_expect_tx(uint32_t a, uint32_t bytes) {
    asm volatile("mbarrier.arrive.expect_tx.shared.b64 _, [%0], %1;"
                 :: "r"(a), "r"(bytes) : "memory");
}
__device__ __forceinline__ void mbar_wait(uint32_t a, uint32_t parity) {
    asm volatile(
        "{\n\t.reg .pred P;\n\t"
        "WL_%=:\n\t"
        "mbarrier.try_wait.parity.acquire.cta.shared::cta.b64 P, [%0], %1, 0x989680;\n\t"
        "@P bra.uni WD_%=;\n\t"
        "bra.uni WL_%=;\n\t"
        "WD_%=:\n\t}"
        :: "r"(a), "r"(parity) : "memory");
}
__device__ __forceinline__ void tma_ld_2d(uint32_t sdst, const CUtensorMap* m,
                                          int cx, int cy, uint32_t mbar) {
    asm volatile(
        "cp.async.bulk.tensor.2d.shared::cta.global.tile.mbarrier::complete_tx::bytes "
        "[%0], [%1, {%2, %3}], [%4];"
        :: "r"(sdst), "l"(m), "r"(cx), "r"(cy), "r"(mbar) : "memory");
}

// ============ tf32 MMA GEMM body (3-stage) ===================================
#define TST 3
#define TWS 36
#define TAS 36
#define TGEMM_SMEM (TST * 128 * TWS * 4 + TST * 64 * TAS * 4)

template <bool RELU>
__device__ __forceinline__ void gemm_tf32_body(
    const float* __restrict__ A, const float* __restrict__ W,
    float* __restrict__ C, int N, int K, int n0, int kbase, int NIT) {
    extern __shared__ unsigned char dyn[];
    float* sW = (float*)dyn;
    float* sA = (float*)(dyn + TST * 128 * TWS * 4);

    const int tid = threadIdx.x;
    const int wid = tid >> 5, lane = tid & 31;
    const int wm = wid & 1, wn = wid >> 1;
    const int g = lane >> 2, t = lane & 3;

    float acc[2][4][4];
#pragma unroll
    for (int i = 0; i < 2; i++)
#pragma unroll
        for (int j = 0; j < 4; j++)
#pragma unroll
            for (int c = 0; c < 4; c++) acc[i][j][c] = 0.0f;

    auto load_stage = [&](int s, int k0) {
#pragma unroll
        for (int r = 0; r < 4; r++) {
            int idx = tid + 256 * r;
            int row = idx >> 3, c4 = (idx & 7) << 2;
            bool p = (n0 + row) < N;
            const float* src = W + (size_t)(n0 + row) * K + k0 + c4;
            cp16(sW + ((s * 128 + row) * TWS + c4), p ? src : W, p);
        }
#pragma unroll
        for (int r = 0; r < 2; r++) {
            int idx = tid + 256 * r;
            int row = idx >> 3, c4 = (idx & 7) << 2;
            cp16(sA + ((s * 64 + row) * TAS + c4), A + (size_t)row * K + k0 + c4, true);
        }
    };

    auto compute = [&](int s) {
#pragma unroll
        for (int kb = 0; kb < 32; kb += 8) {
            unsigned a[2][4];
#pragma unroll
            for (int i = 0; i < 2; i++) {
                const float* ar0 = sA + (size_t)(s * 64 + 32 * wm + 16 * i + g) * TAS + kb;
                const float* ar1 = ar0 + 8 * TAS;
                float f0 = ar0[t], f1 = ar1[t], f2 = ar0[t + 4], f3 = ar1[t + 4];
                if (RELU) {
                    f0 = fmaxf(f0, 0.f); f1 = fmaxf(f1, 0.f);
                    f2 = fmaxf(f2, 0.f); f3 = fmaxf(f3, 0.f);
                }
                a[i][0] = f2tf(f0); a[i][1] = f2tf(f1);
                a[i][2] = f2tf(f2); a[i][3] = f2tf(f3);
            }
#pragma unroll
            for (int j = 0; j < 4; j++) {
                const float* wr = sW + (size_t)(s * 128 + 32 * wn + 8 * j + g) * TWS + kb;
                unsigned b0 = f2tf(wr[t]);
                unsigned b1 = f2tf(wr[t + 4]);
#pragma unroll
                for (int i = 0; i < 2; i++) {
                    asm volatile(
                        "mma.sync.aligned.m16n8k8.row.col.f32.tf32.tf32.f32 "
                        "{%0,%1,%2,%3}, {%4,%5,%6,%7}, {%8,%9}, {%0,%1,%2,%3};"
                        : "+f"(acc[i][j][0]), "+f"(acc[i][j][1]),
                          "+f"(acc[i][j][2]), "+f"(acc[i][j][3])
                        : "r"(a[i][0]), "r"(a[i][1]), "r"(a[i][2]), "r"(a[i][3]),
                          "r"(b0), "r"(b1));
                }
            }
        }
    };

#pragma unroll
    for (int s = 0; s < TST - 1; s++) {
        if (s < NIT) load_stage(s, kbase + s * 32);
        asm volatile("cp.async.commit_group;\n");
    }
#pragma unroll 1
    for (int it = 0; it < NIT; it++) {
        int pre = it + TST - 1;
        if (pre < NIT) load_stage(pre % TST, kbase + pre * 32);
        asm volatile("cp.async.commit_group;\n");
        asm volatile("cp.async.wait_group %0;\n" :: "n"(TST - 1));
        __syncthreads();
        compute(it % TST);
        __syncthreads();
    }

#pragma unroll
    for (int i = 0; i < 2; i++) {
        int m = 32 * wm + 16 * i + g;
#pragma unroll
        for (int j = 0; j < 4; j++) {
            int n = n0 + 32 * wn + 8 * j + 2 * t;
            if (n < N) {
                atomicAdd(&C[(size_t)m * N + n],       acc[i][j][0]);
                atomicAdd(&C[(size_t)(m + 8) * N + n], acc[i][j][2]);
            }
            if (n + 1 < N) {
                atomicAdd(&C[(size_t)m * N + n + 1],       acc[i][j][1]);
                atomicAdd(&C[(size_t)(m + 8) * N + n + 1], acc[i][j][3]);
            }
        }
    }
}

template <bool RELU>
__global__ void __launch_bounds__(256, 2)
gemm_tf32_kernel(const float* __restrict__ A,
                 const float* __restrict__ W,
                 float* __restrict__ C,
                 int N, int K, int Kc) {
    gemm_tf32_body<RELU>(A, W, C, N, K, blockIdx.x * 128, blockIdx.y * Kc, Kc >> 5);
}

// -------- pair kernel: w_hh GEMM (384 blocks) + attn GEMM (16 blocks) --------
__global__ void __launch_bounds__(256, 2)
gemm_pair_kernel(const float* __restrict__ hidden,
                 const float* __restrict__ w_hh,
                 float* __restrict__ gh,
                 const float* __restrict__ attn_in,
                 const float* __restrict__ attn_w,
                 float* __restrict__ attn_lg) {
    int b = blockIdx.x;
    if (b < 384) {
        // w_hh: N=G3, K=HD, 24 n-tiles x 16 k-splits (Kc=64 -> 2 iters)
        gemm_tf32_body<false>(hidden, w_hh, gh, G3, HD,
                              (b % 24) * 128, (b / 24) * 64, 2);
    } else {
        // attn: N=L, K=CAT, 1 n-tile x 16 k-splits (Kc=128 -> 4 iters)
        gemm_tf32_body<false>(attn_in, attn_w, attn_lg, L, CAT,
                              0, (b - 384) * 128, 4);
    }
}

// ------------- fused attn softmax + context (float4, L-split, atomic) --------
__global__ void context_fused_kernel(const float* __restrict__ enc,
                                     float* __restrict__ out_attn) {
    int b = blockIdx.x;
    int t = threadIdx.x;   // 256
    __shared__ float aw[L];
    __shared__ float red[8];

    float v = (t < L) ? g_attn_logits[b * L + t] : -INFINITY;
    float m = v;
#pragma unroll
    for (int o = 16; o; o >>= 1) m = fmaxf(m, __shfl_xor_sync(0xffffffffu, m, o));
    if ((t & 31) == 0) red[t >> 5] = m;
    __syncthreads();
    m = red[0];
#pragma unroll
    for (int w = 1; w < 8; w++) m = fmaxf(m, red[w]);
    __syncthreads();
    float e = (t < L) ? expf(v - m) : 0.0f;
    float s = e;
#pragma unroll
    for (int o = 16; o; o >>= 1) s += __shfl_xor_sync(0xffffffffu, s, o);
    if ((t & 31) == 0) red[t >> 5] = s;
    __syncthreads();
    s = 0.0f;
#pragma unroll
    for (int w = 0; w < 8; w++) s += red[w];
    if (t < L) {
        float a = e / s;
        aw[t] = a;
        if (blockIdx.y == 0) out_attn[b * L + t] = a;
    }
    __syncthreads();

    int l0 = blockIdx.y * 16;   // grid.y = 8, 16 l's per block
    const float4* e4 = reinterpret_cast<const float4*>(enc);
    float ax = 0.f, ay = 0.f, az = 0.f, awv = 0.f;
#pragma unroll
    for (int l = l0; l < l0 + 16; l++) {
        float4 vv = e4[((size_t)l * B + b) * 256 + t];
        float a = aw[l];
        ax = fmaf(a, vv.x, ax); ay = fmaf(a, vv.y, ay);
        az = fmaf(a, vv.z, az); awv = fmaf(a, vv.w, awv);
    }
    float* dst = &g_comb_in[b * CAT + EMB + t * 4];
    atomicAdd(dst + 0, ax); atomicAdd(dst + 1, ay);
    atomicAdd(dst + 2, az); atomicAdd(dst + 3, awv);
}

// ---------------- GRU elementwise ---------------------------------------------
__global__ void gru_kernel(const float* __restrict__ hidden,
                           float* __restrict__ hnew_out) {
    int b = blockIdx.x;
    for (int j = threadIdx.x; j < HD; j += blockDim.x) {
        float ir = g_gi[b * G3 + j];
        float iz = g_gi[b * G3 + HD + j];
        float in_ = g_gi[b * G3 + 2 * HD + j];
        float hr = g_gh[b * G3 + j];
        float hz = g_gh[b * G3 + HD + j];
        float hn = g_gh[b * G3 + 2 * HD + j];
        float r = 1.0f / (1.0f + expf(-(ir + hr)));
        float z = 1.0f / (1.0f + expf(-(iz + hz)));
        float n = tanhf(in_ + r * hn);
        float h0 = hidden[b * HD + j];
        float h = (1.0f - z) * n + z * h0;
        hnew_out[b * HD + j] = h;
        g_h_bf16[b * HD + j] = __float2bfloat16(h);
    }
}

// =========== shared epilogue: logits store + log-softmax partials ============
__device__ __forceinline__ void outproj_epilogue(
    float acc[2][4][4], const float* __restrict__ bias, float* __restrict__ C,
    float* statsmem, int n0, int tile, int tid, int wm, int wn, int g, int t) {
    float vmax[2][2], vsum[2][2];
#pragma unroll
    for (int i = 0; i < 2; i++) { vmax[i][0] = vmax[i][1] = -INFINITY; }

#pragma unroll
    for (int i = 0; i < 2; i++) {
        int m = 32 * wm + 16 * i + g;
#pragma unroll
        for (int j = 0; j < 4; j++) {
            int n = n0 + 32 * wn + 8 * j + 2 * t;
            float x00 = -INFINITY, x01 = -INFINITY, x10 = -INFINITY, x11 = -INFINITY;
            if (n < V) {
                float bv = bias[n];
                x00 = acc[i][j][0] + bv;
                x10 = acc[i][j][2] + bv;
                C[(size_t)m * V + n]       = x00;
                C[(size_t)(m + 8) * V + n] = x10;
            }
            if (n + 1 < V) {
                float bv = bias[n + 1];
                x01 = acc[i][j][1] + bv;
                x11 = acc[i][j][3] + bv;
                C[(size_t)m * V + n + 1]       = x01;
                C[(size_t)(m + 8) * V + n + 1] = x11;
            }
            vmax[i][0] = fmaxf(vmax[i][0], fmaxf(x00, x01));
            vmax[i][1] = fmaxf(vmax[i][1], fmaxf(x10, x11));
        }
    }
#pragma unroll
    for (int i = 0; i < 2; i++)
#pragma unroll
        for (int h = 0; h < 2; h++) {
            float x = vmax[i][h];
            x = fmaxf(x, __shfl_xor_sync(0xffffffffu, x, 1));
            x = fmaxf(x, __shfl_xor_sync(0xffffffffu, x, 2));
            vmax[i][h] = x;
        }
#pragma unroll
    for (int i = 0; i < 2; i++) { vsum[i][0] = vsum[i][1] = 0.0f; }
#pragma unroll
    for (int i = 0; i < 2; i++)
#pragma unroll
        for (int j = 0; j < 4; j++) {
            int n = n0 + 32 * wn + 8 * j + 2 * t;
            if (n < V) {
                float bv = bias[n];
                vsum[i][0] += expf(acc[i][j][0] + bv - vmax[i][0]);
                vsum[i][1] += expf(acc[i][j][2] + bv - vmax[i][1]);
            }
            if (n + 1 < V) {
                float bv = bias[n + 1];
                vsum[i][0] += expf(acc[i][j][1] + bv - vmax[i][0]);
                vsum[i][1] += expf(acc[i][j][3] + bv - vmax[i][1]);
            }
        }
#pragma unroll
    for (int i = 0; i < 2; i++)
#pragma unroll
        for (int h = 0; h < 2; h++) {
            float x = vsum[i][h];
            x += __shfl_xor_sync(0xffffffffu, x, 1);
            x += __shfl_xor_sync(0xffffffffu, x, 2);
            vsum[i][h] = x;
        }

    float* sMx = statsmem;
    float* sSm = statsmem + 256;
    __syncthreads();
    if (t == 0) {
#pragma unroll
        for (int i = 0; i < 2; i++)
#pragma unroll
            for (int h = 0; h < 2; h++) {
                int m = 32 * wm + 16 * i + 8 * h + g;
                sMx[wn * 64 + m] = vmax[i][h];
                sSm[wn * 64 + m] = vsum[i][h];
            }
    }
    __syncthreads();
    if (tid < 64) {
        int m = tid;
        float M = sMx[m];
        M = fmaxf(M, sMx[64 + m]);
        M = fmaxf(M, sMx[128 + m]);
        M = fmaxf(M, sMx[192 + m]);
        float S = 0.0f;
#pragma unroll
        for (int w = 0; w < 4; w++)
            S += sSm[w * 64 + m] * expf(sMx[w * 64 + m] - M);
        g_pmax[m * NB_OUT + tile] = M;
        g_psum[m * NB_OUT + tile] = S;
    }
}

// ======== out_proj TMA: 3-stage pipeline, A staged in smem, 3 CTAs/SM ========
#define QST       3
#define QW_BYTES  16384
#define QA_OFF    (QST * QW_BYTES)
#define QSAS      40
#define QA_BYTES  (64 * QSAS * 2)
#define QMBAR_OFF (QA_OFF + QST * QA_BYTES)
#define QSTAT_OFF (QMBAR_OFF + 64)
#define QSMEM     (QSTAT_OFF + 2048)

__global__ void __launch_bounds__(256, 3)
out_proj_tma_kernel(const __grid_constant__ CUtensorMap tmap,
                    const float* __restrict__ bias,
                    float* __restrict__ C) {
    extern __shared__ unsigned char dyn[];
    __nv_bfloat16* sAb = (__nv_bfloat16*)(dyn + QA_OFF);
    uint32_t mbar0 = s2u32(dyn + QMBAR_OFF);
    float* statsmem = (float*)(dyn + QSTAT_OFF);

    const int tid = threadIdx.x;
    const int n0 = blockIdx.x * 128;
    const int wid = tid >> 5, lane = tid & 31;
    const int wm = wid & 1, wn = wid >> 1;
    const int g = lane >> 2, t = lane & 3;

    if (tid == 0) {
#pragma unroll
        for (int s = 0; s < QST; s++) mbar_init(mbar0 + s * 8, 1);
    }
    __syncthreads();

    float acc[2][4][4];
#pragma unroll
    for (int i = 0; i < 2; i++)
#pragma unroll
        for (int j = 0; j < 4; j++)
#pragma unroll
            for (int c = 0; c < 4; c++) acc[i][j][c] = 0.0f;

    auto issue = [&](int it) {
        int s = it % QST;
        if (tid == 0) {
            uint32_t bar = mbar0 + s * 8;
            mbar_expect_tx(bar, QW_BYTES);
            tma_ld_2d(s2u32(dyn) + s * QW_BYTES, &tmap, it * 32, n0, bar);
        }
        int arow = tid >> 2, ac8 = (tid & 3) << 3;
        cp16(sAb + ((s * 64 + arow) * QSAS + ac8),
             g_h_bf16 + (size_t)arow * HD + it * 32 + ac8, true);
    };

    auto compute = [&](int it) {
        int s = it % QST;
        const float* wst = (const float*)(dyn + s * QW_BYTES);
#pragma unroll
        for (int kb = 0; kb < 32; kb += 16) {
            unsigned a[2][4];
#pragma unroll
            for (int i = 0; i < 2; i++) {
                int r = 32 * wm + 16 * i + g;
                const __nv_bfloat16* base = sAb + (size_t)(s * 64) * QSAS;
                a[i][0] = *reinterpret_cast<const unsigned*>(base + r * QSAS + kb + 2 * t);
                a[i][1] = *reinterpret_cast<const unsigned*>(base + (r + 8) * QSAS + kb + 2 * t);
                a[i][2] = *reinterpret_cast<const unsigned*>(base + r * QSAS + kb + 2 * t + 8);
                a[i][3] = *reinterpret_cast<const unsigned*>(base + (r + 8) * QSAS + kb + 2 * t + 8);
            }
#pragma unroll
            for (int j = 0; j < 4; j++) {
                int br = 32 * wn + 8 * j + g;
                const char* wb = (const char*)(wst + br * 32);
                int sw = (br & 7) << 4;
                float2 f01 = *reinterpret_cast<const float2*>(wb + (((kb + 2 * t) * 4) ^ sw));
                float2 f23 = *reinterpret_cast<const float2*>(wb + (((kb + 2 * t + 8) * 4) ^ sw));
                unsigned b0 = packbf(f01.x, f01.y);
                unsigned b1 = packbf(f23.x, f23.y);
#pragma unroll
                for (int i = 0; i < 2; i++) {
                    asm volatile(
                        "mma.sync.aligned.m16n8k16.row.col.f32.bf16.bf16.f32 "
                        "{%0,%1,%2,%3}, {%4,%5,%6,%7}, {%8,%9}, {%0,%1,%2,%3};"
                        : "+f"(acc[i][j][0]), "+f"(acc[i][j][1]),
                          "+f"(acc[i][j][2]), "+f"(acc[i][j][3])
                        : "r"(a[i][0]), "r"(a[i][1]), "r"(a[i][2]), "r"(a[i][3]),
                          "r"(b0), "r"(b1));
                }
            }
        }
    };

#pragma unroll
    for (int s = 0; s < QST - 1; s++) {
        issue(s);
        asm volatile("cp.async.commit_group;\n");
    }

#pragma unroll 1
    for (int it = 0; it < 32; it++) {
        int pre = it + QST - 1;
        if (pre < 32) issue(pre);
        asm volatile("cp.async.commit_group;\n");
        asm volatile("cp.async.wait_group %0;\n" :: "n"(QST - 1));
        mbar_wait(mbar0 + (it % QST) * 8, (it / QST) & 1);
        __syncthreads();
        compute(it);
        __syncthreads();
    }

    outproj_epilogue(acc, bias, C, statsmem, n0, blockIdx.x, tid, wm, wn, g, t);
}

// ======== output projection, cp.async fallback ================================
#define ST  4
#define SWS 36
#define SAS 40
#define GEMM_SMEM (ST * 128 * SWS * 4 + ST * 64 * SAS * 2)

__global__ void __launch_bounds__(256)
out_proj_mma_kernel(const float* __restrict__ W,
                    const float* __restrict__ bias,
                    float* __restrict__ C) {
    extern __shared__ unsigned char dyn[];
    float* sWb = (float*)dyn;
    __nv_bfloat16* sAb = (__nv_bfloat16*)(dyn + ST * 128 * SWS * 4);

    const int tid = threadIdx.x;
    const int n0 = blockIdx.x * 128;
    const int wid = tid >> 5, lane = tid & 31;
    const int wm = wid & 1, wn = wid >> 1;
    const int g = lane >> 2, t = lane & 3;
    const int K = HD;

    float acc[2][4][4];
#pragma unroll
    for (int i = 0; i < 2; i++)
#pragma unroll
        for (int j = 0; j < 4; j++)
#pragma unroll
            for (int c = 0; c < 4; c++) acc[i][j][c] = 0.0f;

    auto load_stage = [&](int s, int k0) {
#pragma unroll
        for (int r = 0; r < 4; r++) {
            int idx = tid + 256 * r;
            int row = idx >> 3, c4 = (idx & 7) << 2;
            bool p = (n0 + row) < V;
            const float* src = W + (size_t)(n0 + row) * K + k0 + c4;
            cp16(sWb + ((s * 128 + row) * SWS + c4), p ? src : W, p);
        }
        int arow = tid >> 2, ac8 = (tid & 3) << 3;
        cp16(sAb + ((s * 64 + arow) * SAS + ac8), g_h_bf16 + (size_t)arow * K + k0 + ac8, true);
    };

    auto compute = [&](int s) {
#pragma unroll
        for (int kb = 0; kb < 32; kb += 16) {
            unsigned a[2][4];
#pragma unroll
            for (int i = 0; i < 2; i++) {
                int r = 32 * wm + 16 * i + g;
                const __nv_bfloat16* base = sAb + (size_t)(s * 64) * SAS;
                a[i][0] = *reinterpret_cast<const unsigned*>(base + r * SAS + kb + 2 * t);
                a[i][1] = *reinterpret_cast<const unsigned*>(base + (r + 8) * SAS + kb + 2 * t);
                a[i][2] = *reinterpret_cast<const unsigned*>(base + r * SAS + kb + 2 * t + 8);
                a[i][3] = *reinterpret_cast<const unsigned*>(base + (r + 8) * SAS + kb + 2 * t + 8);
            }
#pragma unroll
            for (int j = 0; j < 4; j++) {
                int br = 32 * wn + 8 * j + g;
                const float* wrow = sWb + (size_t)(s * 128 + br) * SWS;
                float2 f01 = *reinterpret_cast<const float2*>(wrow + kb + 2 * t);
                float2 f23 = *reinterpret_cast<const float2*>(wrow + kb + 2 * t + 8);
                unsigned b0 = packbf(f01.x, f01.y);
                unsigned b1 = packbf(f23.x, f23.y);
#pragma unroll
                for (int i = 0; i < 2; i++) {
                    asm volatile(
                        "mma.sync.aligned.m16n8k16.row.col.f32.bf16.bf16.f32 "
                        "{%0,%1,%2,%3}, {%4,%5,%6,%7}, {%8,%9}, {%0,%1,%2,%3};"
                        : "+f"(acc[i][j][0]), "+f"(acc[i][j][1]),
                          "+f"(acc[i][j][2]), "+f"(acc[i][j][3])
                        : "r"(a[i][0]), "r"(a[i][1]), "r"(a[i][2]), "r"(a[i][3]),
                          "r"(b0), "r"(b1));
                }
            }
        }
    };

    const int NIT = K / 32;
#pragma unroll
    for (int s = 0; s < ST - 1; s++) {
        load_stage(s, s * 32);
        asm volatile("cp.async.commit_group;\n");
    }
#pragma unroll 1
    for (int it = 0; it < NIT; it++) {
        int pre = it + ST - 1;
        if (pre < NIT) load_stage(pre & (ST - 1), pre * 32);
        asm volatile("cp.async.commit_group;\n");
        asm volatile("cp.async.wait_group %0;\n" :: "n"(ST - 1));
        __syncthreads();
        compute(it & (ST - 1));
        __syncthreads();
    }

    outproj_epilogue(acc, bias, C, (float*)dyn, n0, blockIdx.x, tid, wm, wn, g, t);
}

// ---------------- log_softmax finalize ---------------------------------------
#define NCHF 16
#define CHF  3142
__global__ void ls_final_kernel(float* __restrict__ out) {
    int b = blockIdx.x, c = blockIdx.y, t = threadIdx.x;
    __shared__ float sM[8], sS[8], lse_sh;

    float M = -INFINITY, S = 0.0f;
    for (int k = t; k < NB_OUT; k += 256) {
        float m2 = g_pmax[b * NB_OUT + k], s2 = g_psum[b * NB_OUT + k];
        if (m2 > M) { S = S * expf(M - m2) + s2; M = m2; }
        else        { S += s2 * expf(m2 - M); }
    }
#pragma unroll
    for (int o = 16; o; o >>= 1) {
        float m2 = __shfl_xor_sync(0xffffffffu, M, o);
        float s2 = __shfl_xor_sync(0xffffffffu, S, o);
        if (m2 > M) { S = S * expf(M - m2) + s2; M = m2; }
        else        { S += s2 * expf(m2 - M); }
    }
    if ((t & 31) == 0) { sM[t >> 5] = M; sS[t >> 5] = S; }
    __syncthreads();
    if (t == 0) {
        float Mg = sM[0], Sg = sS[0];
#pragma unroll
        for (int w = 1; w < 8; w++) {
            float m2 = sM[w], s2 = sS[w];
            if (m2 > Mg) { Sg = Sg * expf(Mg - m2) + s2; Mg = m2; }
            else         { Sg += s2 * expf(m2 - Mg); }
        }
        lse_sh = Mg + logf(Sg);
    }
    __syncthreads();
    float lse = lse_sh;

    int s0 = c * CHF, s1 = min(s0 + CHF, V);
    const float* row = &g_logits[(size_t)b * V];
    float* orow = &out[(size_t)b * V];
    int i = s0 + t;
    for (; i + 768 < s1; i += 1024) {
        float v0 = row[i], v1 = row[i + 256], v2 = row[i + 512], v3 = row[i + 768];
        orow[i]       = v0 - lse;
        orow[i + 256] = v1 - lse;
        orow[i + 512] = v2 - lse;
        orow[i + 768] = v3 - lse;
    }
    for (; i < s1; i += 256) orow[i] = row[i] - lse;
}

// ---------------- launcher ---------------------------------------------------
typedef CUresult (*EncodeFn)(CUtensorMap*, CUtensorMapDataType, cuuint32_t,
                             void*, const cuuint64_t*, const cuuint64_t*,
                             const cuuint32_t*, const cuuint32_t*,
                             CUtensorMapInterleave, CUtensorMapSwizzle,
                             CUtensorMapL2promotion, CUtensorMapFloatOOBfill);

extern "C" void kernel_launch(void* const* d_in, const int* in_sizes, int n_in,
                              void* d_out, int out_size) {
    const int*   input_tensor = (const int*)  d_in[0];
    const float* hidden       = (const float*)d_in[1];
    const float* enc          = (const float*)d_in[2];
    const float* emb_table    = (const float*)d_in[4];
    const float* attn_w       = (const float*)d_in[5];
    const float* attn_b       = (const float*)d_in[6];
    const float* comb_w       = (const float*)d_in[7];
    const float* comb_b       = (const float*)d_in[8];
    const float* w_ih         = (const float*)d_in[9];
    const float* w_hh         = (const float*)d_in[10];
    const float* b_ih         = (const float*)d_in[11];
    const float* b_hh         = (const float*)d_in[12];
    const float* out_w        = (const float*)d_in[13];
    const float* out_b        = (const float*)d_in[14];

    float* out        = (float*)d_out;
    float* out_logsm  = out;
    float* out_hnew   = out + (size_t)B * V;
    float* out_attn   = out + (size_t)B * V + (size_t)B * HD;

    float* d_attn_in; cudaGetSymbolAddress((void**)&d_attn_in, g_attn_in);
    float* d_comb_in; cudaGetSymbolAddress((void**)&d_comb_in, g_comb_in);
    float* d_logits;  cudaGetSymbolAddress((void**)&d_logits,  g_logits);
    float* d_x;       cudaGetSymbolAddress((void**)&d_x,       g_x);
    float* d_gi;      cudaGetSymbolAddress((void**)&d_gi,      g_gi);
    float* d_gh;      cudaGetSymbolAddress((void**)&d_gh,      g_gh);
    float* d_attn_lg; cudaGetSymbolAddress((void**)&d_attn_lg, g_attn_logits);

    static bool attr_set = false;
    if (!attr_set) {
        cudaFuncSetAttribute(out_proj_mma_kernel,
                             cudaFuncAttributeMaxDynamicSharedMemorySize, GEMM_SMEM);
        cudaFuncSetAttribute(out_proj_tma_kernel,
                             cudaFuncAttributeMaxDynamicSharedMemorySize, QSMEM);
        cudaFuncSetAttribute(gemm_tf32_kernel<false>,
                             cudaFuncAttributeMaxDynamicSharedMemorySize, TGEMM_SMEM);
        cudaFuncSetAttribute(gemm_tf32_kernel<true>,
                             cudaFuncAttributeMaxDynamicSharedMemorySize, TGEMM_SMEM);
        cudaFuncSetAttribute(gemm_pair_kernel,
                             cudaFuncAttributeMaxDynamicSharedMemorySize, TGEMM_SMEM);
        attr_set = true;
    }

    CUtensorMap tmap;
    bool use_tma = false;
    {
        void* h = dlopen("libcuda.so.1", RTLD_LAZY | RTLD_NOLOAD);
        if (!h) h = dlopen("libcuda.so.1", RTLD_LAZY);
        if (h) {
            EncodeFn fn = (EncodeFn)dlsym(h, "cuTensorMapEncodeTiled");
            if (fn) {
                cuuint64_t dims[2]    = {(cuuint64_t)HD, (cuuint64_t)V};
                cuuint64_t strides[1] = {(cuuint64_t)HD * sizeof(float)};
                cuuint32_t box[2]     = {32, 128};
                cuuint32_t estr[2]    = {1, 1};
                CUresult r = fn(&tmap, CU_TENSOR_MAP_DATA_TYPE_FLOAT32, 2,
                                (void*)out_w, dims, strides, box, estr,
                                CU_TENSOR_MAP_INTERLEAVE_NONE,
                                CU_TENSOR_MAP_SWIZZLE_128B,
                                CU_TENSOR_MAP_L2_PROMOTION_L2_128B,
                                CU_TENSOR_MAP_FLOAT_OOB_FILL_NONE);
                use_tma = (r == CUDA_SUCCESS);
            }
        }
    }

    // 1. embed + concat + bias/zero init
    prep_kernel<<<B + NBIAS, 256>>>(input_tensor, hidden, emb_table,
                                    attn_b, comb_b, b_ih, b_hh);

    // 2. w_hh GEMM + attention-logits GEMM (one launch, 400 blocks)
    gemm_pair_kernel<<<400, 256, TGEMM_SMEM>>>(hidden, w_hh, d_gh,
                                               d_attn_in, attn_w, d_attn_lg);

    // 3. fused softmax + context
    context_fused_kernel<<<dim3(B, 8), 256>>>(enc, out_attn);

    // 4. comb GEMM (32 k-splits -> 256 blocks, NIT=2)
    gemm_tf32_kernel<false><<<dim3(HE / 128, 32), 256, TGEMM_SMEM>>>(
        d_comb_in, comb_w, d_x, HE, CAT, CAT / 32);

    // 5. GRU input GEMM (relu folded, 16 k-splits -> 384 blocks, NIT=2)
    gemm_tf32_kernel<true><<<dim3(G3 / 128, 16), 256, TGEMM_SMEM>>>(
        d_x, w_ih, d_gi, G3, HE, HE / 16);

    // 6. GRU elementwise
    gru_kernel<<<B, 256>>>(hidden, out_hnew);

    // 7. output projection + fused log-softmax partials
    if (use_tma) {
        out_proj_tma_kernel<<<NB_OUT, 256, QSMEM>>>(tmap, out_b, d_logits);
    } else {
        out_proj_mma_kernel<<<NB_OUT, 256, GEMM_SMEM>>>(out_w, out_b, d_logits);
    }

    // 8. log-softmax finalize
    ls_final_kernel<<<dim3(B, NCHF), 256>>>(out_logsm);
}

// round 17
// speedup vs baseline: 1.0535x; 1.0535x over previous
#include <cuda_runtime.h>
#include <cuda.h>
#include <cuda_bf16.h>
#include <math.h>
#include <stdint.h>
#include <dlfcn.h>

#define V   50257
#define EMB 1024
#define HD  1024
#define HE  1024
#define L   128
#define B   64
#define CAT 2048
#define G3  3072

// ---------------- scratch ----------------------------------------------------
__device__ float         g_attn_in[B * CAT];
__device__ float         g_comb_in[B * CAT];
__device__ float         g_attn_logits[B * L];
__device__ float         g_x[B * HE];
__device__ float         g_gi[B * G3];
__device__ float         g_gh[B * G3];
__device__ float         g_logits[B * V];
__device__ __nv_bfloat16 g_h_bf16[B * HD];
#define NB_OUT 393
__device__ float         g_pmax[B * NB_OUT];
__device__ float         g_psum[B * NB_OUT];

// ---------------- fused embed + concat + bias/zero init (float4) -------------
#define SEG0 (B * L)
#define SEG1 (SEG0 + B * HE)
#define SEG2 (SEG1 + B * G3)
#define SEG3 (SEG2 + B * G3)
#define SEG4 (SEG3 + B * HE)
#define NBIAS4 (SEG4 / 4 / 256)   // 520
__global__ void prep_kernel(const int* __restrict__ idx,
                            const float* __restrict__ hidden,
                            const float* __restrict__ emb_table,
                            const float* __restrict__ attn_b,
                            const float* __restrict__ comb_b,
                            const float* __restrict__ b_ih,
                            const float* __restrict__ b_hh) {
    int blk = blockIdx.x;
    if (blk < B) {
        int b = blk;
        int row = idx[b];
        int k = threadIdx.x * 4;   // 256 threads x 4 = EMB
        float4 e = *reinterpret_cast<const float4*>(&emb_table[(size_t)row * EMB + k]);
        *reinterpret_cast<float4*>(&g_attn_in[b * CAT + k]) = e;
        *reinterpret_cast<float4*>(&g_comb_in[b * CAT + k]) = e;
        float4 h = *reinterpret_cast<const float4*>(&hidden[b * HD + k]);
        *reinterpret_cast<float4*>(&g_attn_in[b * CAT + EMB + k]) = h;
    } else {
        int i = ((blk - B) * 256 + threadIdx.x) * 4;
        if (i < SEG0) {
            *reinterpret_cast<float4*>(&g_attn_logits[i]) =
                *reinterpret_cast<const float4*>(&attn_b[i & (L - 1)]);
        } else if (i < SEG1) {
            int j = i - SEG0;
            *reinterpret_cast<float4*>(&g_x[j]) =
                *reinterpret_cast<const float4*>(&comb_b[j & (HE - 1)]);
        } else if (i < SEG2) {
            int j = i - SEG1;
            *reinterpret_cast<float4*>(&g_gi[j]) =
                *reinterpret_cast<const float4*>(&b_ih[j % G3]);
        } else if (i < SEG3) {
            int j = i - SEG2;
            *reinterpret_cast<float4*>(&g_gh[j]) =
                *reinterpret_cast<const float4*>(&b_hh[j % G3]);
        } else if (i < SEG4) {
            int j = i - SEG3;
            int b = j / HE, e = j % HE;
            *reinterpret_cast<float4*>(&g_comb_in[b * CAT + EMB + e]) =
                make_float4(0.f, 0.f, 0.f, 0.f);
        }
    }
}

// ---------------- helpers ----------------------------------------------------
__device__ __forceinline__ void cp16(void* saddr, const void* g, bool p) {
    uint32_t s = (uint32_t)__cvta_generic_to_shared(saddr);
    int sz = p ? 16 : 0;
    asm volatile("cp.async.cg.shared.global [%0], [%1], 16, %2;\n"
                 :: "r"(s), "l"(g), "r"(sz));
}
__device__ __forceinline__ unsigned packbf(float a, float b) {
    __nv_bfloat162 p = __float22bfloat162_rn(make_float2(a, b));
    return *reinterpret_cast<unsigned*>(&p);
}
__device__ __forceinline__ unsigned f2tf(float f) {
    unsigned u;
    asm("cvt.rna.tf32.f32 %0, %1;" : "=r"(u) : "f"(f));
    return u;
}
__device__ __forceinline__ uint32_t s2u32(const void* p) {
    return (uint32_t)__cvta_generic_to_shared(p);
}
__device__ __forceinline__ void mbar_init(uint32_t a, uint32_t cnt) {
    asm volatile("mbarrier.init.shared.b64 [%0], %1;" :: "r"(a), "r"(cnt) : "memory");
}
__device__ __forceinline__ void mbar_expect_tx(uint32_t a, uint32_t bytes) {
    asm volatile("mbarrier.arrive.expect_tx.shared.b64 _, [%0], %1;"
                 :: "r"(a), "r"(bytes) : "memory");
}
__device__ __forceinline__ void mbar_wait(uint32_t a, uint32_t parity) {
    asm volatile(
        "{\n\t.reg .pred P;\n\t"
        "WL_%=:\n\t"
        "mbarrier.try_wait.parity.acquire.cta.shared::cta.b64 P, [%0], %1, 0x989680;\n\t"
        "@P bra.uni WD_%=;\n\t"
        "bra.uni WL_%=;\n\t"
        "WD_%=:\n\t}"
        :: "r"(a), "r"(parity) : "memory");
}
__device__ __forceinline__ void tma_ld_2d(uint32_t sdst, const CUtensorMap* m,
                                          int cx, int cy, uint32_t mbar) {
    asm volatile(
        "cp.async.bulk.tensor.2d.shared::cta.global.tile.mbarrier::complete_tx::bytes "
        "[%0], [%1, {%2, %3}], [%4];"
        :: "r"(sdst), "l"(m), "r"(cx), "r"(cy), "r"(mbar) : "memory");
}

// ============ tf32 MMA GEMM body (3-stage) ===================================
#define TST 3
#define TWS 36
#define TAS 36
#define TGEMM_SMEM (TST * 128 * TWS * 4 + TST * 64 * TAS * 4)

template <bool RELU>
__device__ __forceinline__ void gemm_tf32_body(
    const float* __restrict__ A, const float* __restrict__ W,
    float* __restrict__ C, int N, int K, int n0, int kbase, int NIT) {
    extern __shared__ unsigned char dyn[];
    float* sW = (float*)dyn;
    float* sA = (float*)(dyn + TST * 128 * TWS * 4);

    const int tid = threadIdx.x;
    const int wid = tid >> 5, lane = tid & 31;
    const int wm = wid & 1, wn = wid >> 1;
    const int g = lane >> 2, t = lane & 3;

    float acc[2][4][4];
#pragma unroll
    for (int i = 0; i < 2; i++)
#pragma unroll
        for (int j = 0; j < 4; j++)
#pragma unroll
            for (int c = 0; c < 4; c++) acc[i][j][c] = 0.0f;

    auto load_stage = [&](int s, int k0) {
#pragma unroll
        for (int r = 0; r < 4; r++) {
            int idx = tid + 256 * r;
            int row = idx >> 3, c4 = (idx & 7) << 2;
            bool p = (n0 + row) < N;
            const float* src = W + (size_t)(n0 + row) * K + k0 + c4;
            cp16(sW + ((s * 128 + row) * TWS + c4), p ? src : W, p);
        }
#pragma unroll
        for (int r = 0; r < 2; r++) {
            int idx = tid + 256 * r;
            int row = idx >> 3, c4 = (idx & 7) << 2;
            cp16(sA + ((s * 64 + row) * TAS + c4), A + (size_t)row * K + k0 + c4, true);
        }
    };

    auto compute = [&](int s) {
#pragma unroll
        for (int kb = 0; kb < 32; kb += 8) {
            unsigned a[2][4];
#pragma unroll
            for (int i = 0; i < 2; i++) {
                const float* ar0 = sA + (size_t)(s * 64 + 32 * wm + 16 * i + g) * TAS + kb;
                const float* ar1 = ar0 + 8 * TAS;
                float f0 = ar0[t], f1 = ar1[t], f2 = ar0[t + 4], f3 = ar1[t + 4];
                if (RELU) {
                    f0 = fmaxf(f0, 0.f); f1 = fmaxf(f1, 0.f);
                    f2 = fmaxf(f2, 0.f); f3 = fmaxf(f3, 0.f);
                }
                a[i][0] = f2tf(f0); a[i][1] = f2tf(f1);
                a[i][2] = f2tf(f2); a[i][3] = f2tf(f3);
            }
#pragma unroll
            for (int j = 0; j < 4; j++) {
                const float* wr = sW + (size_t)(s * 128 + 32 * wn + 8 * j + g) * TWS + kb;
                unsigned b0 = f2tf(wr[t]);
                unsigned b1 = f2tf(wr[t + 4]);
#pragma unroll
                for (int i = 0; i < 2; i++) {
                    asm volatile(
                        "mma.sync.aligned.m16n8k8.row.col.f32.tf32.tf32.f32 "
                        "{%0,%1,%2,%3}, {%4,%5,%6,%7}, {%8,%9}, {%0,%1,%2,%3};"
                        : "+f"(acc[i][j][0]), "+f"(acc[i][j][1]),
                          "+f"(acc[i][j][2]), "+f"(acc[i][j][3])
                        : "r"(a[i][0]), "r"(a[i][1]), "r"(a[i][2]), "r"(a[i][3]),
                          "r"(b0), "r"(b1));
                }
            }
        }
    };

#pragma unroll
    for (int s = 0; s < TST - 1; s++) {
        if (s < NIT) load_stage(s, kbase + s * 32);
        asm volatile("cp.async.commit_group;\n");
    }
#pragma unroll 1
    for (int it = 0; it < NIT; it++) {
        int pre = it + TST - 1;
        if (pre < NIT) load_stage(pre % TST, kbase + pre * 32);
        asm volatile("cp.async.commit_group;\n");
        asm volatile("cp.async.wait_group %0;\n" :: "n"(TST - 1));
        __syncthreads();
        compute(it % TST);
        __syncthreads();
    }

#pragma unroll
    for (int i = 0; i < 2; i++) {
        int m = 32 * wm + 16 * i + g;
#pragma unroll
        for (int j = 0; j < 4; j++) {
            int n = n0 + 32 * wn + 8 * j + 2 * t;
            if (n < N) {
                atomicAdd(&C[(size_t)m * N + n],       acc[i][j][0]);
                atomicAdd(&C[(size_t)(m + 8) * N + n], acc[i][j][2]);
            }
            if (n + 1 < N) {
                atomicAdd(&C[(size_t)m * N + n + 1],       acc[i][j][1]);
                atomicAdd(&C[(size_t)(m + 8) * N + n + 1], acc[i][j][3]);
            }
        }
    }
}

template <bool RELU>
__global__ void __launch_bounds__(256, 2)
gemm_tf32_kernel(const float* __restrict__ A,
                 const float* __restrict__ W,
                 float* __restrict__ C,
                 int N, int K, int Kc) {
    gemm_tf32_body<RELU>(A, W, C, N, K, blockIdx.x * 128, blockIdx.y * Kc, Kc >> 5);
}

// -------- pair kernel: w_hh GEMM (192 blocks) + attn GEMM (16 blocks) --------
__global__ void __launch_bounds__(256, 2)
gemm_pair_kernel(const float* __restrict__ hidden,
                 const float* __restrict__ w_hh,
                 float* __restrict__ gh,
                 const float* __restrict__ attn_in,
                 const float* __restrict__ attn_w,
                 float* __restrict__ attn_lg) {
    int b = blockIdx.x;
    if (b < 192) {
        // w_hh: N=G3, K=HD, 24 n-tiles x 8 k-splits (Kc=128 -> 4 iters)
        gemm_tf32_body<false>(hidden, w_hh, gh, G3, HD,
                              (b % 24) * 128, (b / 24) * 128, 4);
    } else {
        // attn: N=L, K=CAT, 1 n-tile x 16 k-splits (Kc=128 -> 4 iters)
        gemm_tf32_body<false>(attn_in, attn_w, attn_lg, L, CAT,
                              0, (b - 192) * 128, 4);
    }
}

// ------------- fused attn softmax + context (float4, L-split, atomic) --------
__global__ void context_fused_kernel(const float* __restrict__ enc,
                                     float* __restrict__ out_attn) {
    int b = blockIdx.x;
    int t = threadIdx.x;   // 256
    __shared__ float aw[L];
    __shared__ float red[8];

    float v = (t < L) ? g_attn_logits[b * L + t] : -INFINITY;
    float m = v;
#pragma unroll
    for (int o = 16; o; o >>= 1) m = fmaxf(m, __shfl_xor_sync(0xffffffffu, m, o));
    if ((t & 31) == 0) red[t >> 5] = m;
    __syncthreads();
    m = red[0];
#pragma unroll
    for (int w = 1; w < 8; w++) m = fmaxf(m, red[w]);
    __syncthreads();
    float e = (t < L) ? expf(v - m) : 0.0f;
    float s = e;
#pragma unroll
    for (int o = 16; o; o >>= 1) s += __shfl_xor_sync(0xffffffffu, s, o);
    if ((t & 31) == 0) red[t >> 5] = s;
    __syncthreads();
    s = 0.0f;
#pragma unroll
    for (int w = 0; w < 8; w++) s += red[w];
    if (t < L) {
        float a = e / s;
        aw[t] = a;
        if (blockIdx.y == 0) out_attn[b * L + t] = a;
    }
    __syncthreads();

    int l0 = blockIdx.y * 16;   // grid.y = 8, 16 l's per block
    const float4* e4 = reinterpret_cast<const float4*>(enc);
    float ax = 0.f, ay = 0.f, az = 0.f, awv = 0.f;
#pragma unroll
    for (int l = l0; l < l0 + 16; l++) {
        float4 vv = e4[((size_t)l * B + b) * 256 + t];
        float a = aw[l];
        ax = fmaf(a, vv.x, ax); ay = fmaf(a, vv.y, ay);
        az = fmaf(a, vv.z, az); awv = fmaf(a, vv.w, awv);
    }
    float* dst = &g_comb_in[b * CAT + EMB + t * 4];
    atomicAdd(dst + 0, ax); atomicAdd(dst + 1, ay);
    atomicAdd(dst + 2, az); atomicAdd(dst + 3, awv);
}

// ---------------- GRU elementwise ---------------------------------------------
__global__ void gru_kernel(const float* __restrict__ hidden,
                           float* __restrict__ hnew_out) {
    int b = blockIdx.x;
    for (int j = threadIdx.x; j < HD; j += blockDim.x) {
        float ir = g_gi[b * G3 + j];
        float iz = g_gi[b * G3 + HD + j];
        float in_ = g_gi[b * G3 + 2 * HD + j];
        float hr = g_gh[b * G3 + j];
        float hz = g_gh[b * G3 + HD + j];
        float hn = g_gh[b * G3 + 2 * HD + j];
        float r = 1.0f / (1.0f + expf(-(ir + hr)));
        float z = 1.0f / (1.0f + expf(-(iz + hz)));
        float n = tanhf(in_ + r * hn);
        float h0 = hidden[b * HD + j];
        float h = (1.0f - z) * n + z * h0;
        hnew_out[b * HD + j] = h;
        g_h_bf16[b * HD + j] = __float2bfloat16(h);
    }
}

// =========== shared epilogue: logits store + log-softmax partials ============
__device__ __forceinline__ void outproj_epilogue(
    float acc[2][4][4], const float* __restrict__ bias, float* __restrict__ C,
    float* statsmem, int n0, int tile, int tid, int wm, int wn, int g, int t) {
    float vmax[2][2], vsum[2][2];
#pragma unroll
    for (int i = 0; i < 2; i++) { vmax[i][0] = vmax[i][1] = -INFINITY; }

#pragma unroll
    for (int i = 0; i < 2; i++) {
        int m = 32 * wm + 16 * i + g;
#pragma unroll
        for (int j = 0; j < 4; j++) {
            int n = n0 + 32 * wn + 8 * j + 2 * t;
            float x00 = -INFINITY, x01 = -INFINITY, x10 = -INFINITY, x11 = -INFINITY;
            if (n < V) {
                float bv = bias[n];
                x00 = acc[i][j][0] + bv;
                x10 = acc[i][j][2] + bv;
                C[(size_t)m * V + n]       = x00;
                C[(size_t)(m + 8) * V + n] = x10;
            }
            if (n + 1 < V) {
                float bv = bias[n + 1];
                x01 = acc[i][j][1] + bv;
                x11 = acc[i][j][3] + bv;
                C[(size_t)m * V + n + 1]       = x01;
                C[(size_t)(m + 8) * V + n + 1] = x11;
            }
            vmax[i][0] = fmaxf(vmax[i][0], fmaxf(x00, x01));
            vmax[i][1] = fmaxf(vmax[i][1], fmaxf(x10, x11));
        }
    }
#pragma unroll
    for (int i = 0; i < 2; i++)
#pragma unroll
        for (int h = 0; h < 2; h++) {
            float x = vmax[i][h];
            x = fmaxf(x, __shfl_xor_sync(0xffffffffu, x, 1));
            x = fmaxf(x, __shfl_xor_sync(0xffffffffu, x, 2));
            vmax[i][h] = x;
        }
#pragma unroll
    for (int i = 0; i < 2; i++) { vsum[i][0] = vsum[i][1] = 0.0f; }
#pragma unroll
    for (int i = 0; i < 2; i++)
#pragma unroll
        for (int j = 0; j < 4; j++) {
            int n = n0 + 32 * wn + 8 * j + 2 * t;
            if (n < V) {
                float bv = bias[n];
                vsum[i][0] += expf(acc[i][j][0] + bv - vmax[i][0]);
                vsum[i][1] += expf(acc[i][j][2] + bv - vmax[i][1]);
            }
            if (n + 1 < V) {
                float bv = bias[n + 1];
                vsum[i][0] += expf(acc[i][j][1] + bv - vmax[i][0]);
                vsum[i][1] += expf(acc[i][j][3] + bv - vmax[i][1]);
            }
        }
#pragma unroll
    for (int i = 0; i < 2; i++)
#pragma unroll
        for (int h = 0; h < 2; h++) {
            float x = vsum[i][h];
            x += __shfl_xor_sync(0xffffffffu, x, 1);
            x += __shfl_xor_sync(0xffffffffu, x, 2);
            vsum[i][h] = x;
        }

    float* sMx = statsmem;
    float* sSm = statsmem + 256;
    __syncthreads();
    if (t == 0) {
#pragma unroll
        for (int i = 0; i < 2; i++)
#pragma unroll
            for (int h = 0; h < 2; h++) {
                int m = 32 * wm + 16 * i + 8 * h + g;
                sMx[wn * 64 + m] = vmax[i][h];
                sSm[wn * 64 + m] = vsum[i][h];
            }
    }
    __syncthreads();
    if (tid < 64) {
        int m = tid;
        float M = sMx[m];
        M = fmaxf(M, sMx[64 + m]);
        M = fmaxf(M, sMx[128 + m]);
        M = fmaxf(M, sMx[192 + m]);
        float S = 0.0f;
#pragma unroll
        for (int w = 0; w < 4; w++)
            S += sSm[w * 64 + m] * expf(sMx[w * 64 + m] - M);
        g_pmax[m * NB_OUT + tile] = M;
        g_psum[m * NB_OUT + tile] = S;
    }
}

// ======== out_proj TMA: 3-stage pipeline, A staged in smem, 3 CTAs/SM ========
#define QST       3
#define QW_BYTES  16384
#define QA_OFF    (QST * QW_BYTES)
#define QSAS      40
#define QA_BYTES  (64 * QSAS * 2)
#define QMBAR_OFF (QA_OFF + QST * QA_BYTES)
#define QSTAT_OFF (QMBAR_OFF + 64)
#define QSMEM     (QSTAT_OFF + 2048)

__global__ void __launch_bounds__(256, 3)
out_proj_tma_kernel(const __grid_constant__ CUtensorMap tmap,
                    const float* __restrict__ bias,
                    float* __restrict__ C) {
    extern __shared__ unsigned char dyn[];
    __nv_bfloat16* sAb = (__nv_bfloat16*)(dyn + QA_OFF);
    uint32_t mbar0 = s2u32(dyn + QMBAR_OFF);
    float* statsmem = (float*)(dyn + QSTAT_OFF);

    const int tid = threadIdx.x;
    const int n0 = blockIdx.x * 128;
    const int wid = tid >> 5, lane = tid & 31;
    const int wm = wid & 1, wn = wid >> 1;
    const int g = lane >> 2, t = lane & 3;

    if (tid == 0) {
#pragma unroll
        for (int s = 0; s < QST; s++) mbar_init(mbar0 + s * 8, 1);
    }
    __syncthreads();

    float acc[2][4][4];
#pragma unroll
    for (int i = 0; i < 2; i++)
#pragma unroll
        for (int j = 0; j < 4; j++)
#pragma unroll
            for (int c = 0; c < 4; c++) acc[i][j][c] = 0.0f;

    auto issue = [&](int it) {
        int s = it % QST;
        if (tid == 0) {
            uint32_t bar = mbar0 + s * 8;
            mbar_expect_tx(bar, QW_BYTES);
            tma_ld_2d(s2u32(dyn) + s * QW_BYTES, &tmap, it * 32, n0, bar);
        }
        int arow = tid >> 2, ac8 = (tid & 3) << 3;
        cp16(sAb + ((s * 64 + arow) * QSAS + ac8),
             g_h_bf16 + (size_t)arow * HD + it * 32 + ac8, true);
    };

    auto compute = [&](int it) {
        int s = it % QST;
        const float* wst = (const float*)(dyn + s * QW_BYTES);
#pragma unroll
        for (int kb = 0; kb < 32; kb += 16) {
            unsigned a[2][4];
#pragma unroll
            for (int i = 0; i < 2; i++) {
                int r = 32 * wm + 16 * i + g;
                const __nv_bfloat16* base = sAb + (size_t)(s * 64) * QSAS;
                a[i][0] = *reinterpret_cast<const unsigned*>(base + r * QSAS + kb + 2 * t);
                a[i][1] = *reinterpret_cast<const unsigned*>(base + (r + 8) * QSAS + kb + 2 * t);
                a[i][2] = *reinterpret_cast<const unsigned*>(base + r * QSAS + kb + 2 * t + 8);
                a[i][3] = *reinterpret_cast<const unsigned*>(base + (r + 8) * QSAS + kb + 2 * t + 8);
            }
#pragma unroll
            for (int j = 0; j < 4; j++) {
                int br = 32 * wn + 8 * j + g;
                const char* wb = (const char*)(wst + br * 32);
                int sw = (br & 7) << 4;
                float2 f01 = *reinterpret_cast<const float2*>(wb + (((kb + 2 * t) * 4) ^ sw));
                float2 f23 = *reinterpret_cast<const float2*>(wb + (((kb + 2 * t + 8) * 4) ^ sw));
                unsigned b0 = packbf(f01.x, f01.y);
                unsigned b1 = packbf(f23.x, f23.y);
#pragma unroll
                for (int i = 0; i < 2; i++) {
                    asm volatile(
                        "mma.sync.aligned.m16n8k16.row.col.f32.bf16.bf16.f32 "
                        "{%0,%1,%2,%3}, {%4,%5,%6,%7}, {%8,%9}, {%0,%1,%2,%3};"
                        : "+f"(acc[i][j][0]), "+f"(acc[i][j][1]),
                          "+f"(acc[i][j][2]), "+f"(acc[i][j][3])
                        : "r"(a[i][0]), "r"(a[i][1]), "r"(a[i][2]), "r"(a[i][3]),
                          "r"(b0), "r"(b1));
                }
            }
        }
    };

#pragma unroll
    for (int s = 0; s < QST - 1; s++) {
        issue(s);
        asm volatile("cp.async.commit_group;\n");
    }

#pragma unroll 1
    for (int it = 0; it < 32; it++) {
        int pre = it + QST - 1;
        if (pre < 32) issue(pre);
        asm volatile("cp.async.commit_group;\n");
        asm volatile("cp.async.wait_group %0;\n" :: "n"(QST - 1));
        mbar_wait(mbar0 + (it % QST) * 8, (it / QST) & 1);
        __syncthreads();
        compute(it);
        __syncthreads();
    }

    outproj_epilogue(acc, bias, C, statsmem, n0, blockIdx.x, tid, wm, wn, g, t);
}

// ======== output projection, cp.async fallback ================================
#define ST  4
#define SWS 36
#define SAS 40
#define GEMM_SMEM (ST * 128 * SWS * 4 + ST * 64 * SAS * 2)

__global__ void __launch_bounds__(256)
out_proj_mma_kernel(const float* __restrict__ W,
                    const float* __restrict__ bias,
                    float* __restrict__ C) {
    extern __shared__ unsigned char dyn[];
    float* sWb = (float*)dyn;
    __nv_bfloat16* sAb = (__nv_bfloat16*)(dyn + ST * 128 * SWS * 4);

    const int tid = threadIdx.x;
    const int n0 = blockIdx.x * 128;
    const int wid = tid >> 5, lane = tid & 31;
    const int wm = wid & 1, wn = wid >> 1;
    const int g = lane >> 2, t = lane & 3;
    const int K = HD;

    float acc[2][4][4];
#pragma unroll
    for (int i = 0; i < 2; i++)
#pragma unroll
        for (int j = 0; j < 4; j++)
#pragma unroll
            for (int c = 0; c < 4; c++) acc[i][j][c] = 0.0f;

    auto load_stage = [&](int s, int k0) {
#pragma unroll
        for (int r = 0; r < 4; r++) {
            int idx = tid + 256 * r;
            int row = idx >> 3, c4 = (idx & 7) << 2;
            bool p = (n0 + row) < V;
            const float* src = W + (size_t)(n0 + row) * K + k0 + c4;
            cp16(sWb + ((s * 128 + row) * SWS + c4), p ? src : W, p);
        }
        int arow = tid >> 2, ac8 = (tid & 3) << 3;
        cp16(sAb + ((s * 64 + arow) * SAS + ac8), g_h_bf16 + (size_t)arow * K + k0 + ac8, true);
    };

    auto compute = [&](int s) {
#pragma unroll
        for (int kb = 0; kb < 32; kb += 16) {
            unsigned a[2][4];
#pragma unroll
            for (int i = 0; i < 2; i++) {
                int r = 32 * wm + 16 * i + g;
                const __nv_bfloat16* base = sAb + (size_t)(s * 64) * SAS;
                a[i][0] = *reinterpret_cast<const unsigned*>(base + r * SAS + kb + 2 * t);
                a[i][1] = *reinterpret_cast<const unsigned*>(base + (r + 8) * SAS + kb + 2 * t);
                a[i][2] = *reinterpret_cast<const unsigned*>(base + r * SAS + kb + 2 * t + 8);
                a[i][3] = *reinterpret_cast<const unsigned*>(base + (r + 8) * SAS + kb + 2 * t + 8);
            }
#pragma unroll
            for (int j = 0; j < 4; j++) {
                int br = 32 * wn + 8 * j + g;
                const float* wrow = sWb + (size_t)(s * 128 + br) * SWS;
                float2 f01 = *reinterpret_cast<const float2*>(wrow + kb + 2 * t);
                float2 f23 = *reinterpret_cast<const float2*>(wrow + kb + 2 * t + 8);
                unsigned b0 = packbf(f01.x, f01.y);
                unsigned b1 = packbf(f23.x, f23.y);
#pragma unroll
                for (int i = 0; i < 2; i++) {
                    asm volatile(
                        "mma.sync.aligned.m16n8k16.row.col.f32.bf16.bf16.f32 "
                        "{%0,%1,%2,%3}, {%4,%5,%6,%7}, {%8,%9}, {%0,%1,%2,%3};"
                        : "+f"(acc[i][j][0]), "+f"(acc[i][j][1]),
                          "+f"(acc[i][j][2]), "+f"(acc[i][j][3])
                        : "r"(a[i][0]), "r"(a[i][1]), "r"(a[i][2]), "r"(a[i][3]),
                          "r"(b0), "r"(b1));
                }
            }
        }
    };

    const int NIT = K / 32;
#pragma unroll
    for (int s = 0; s < ST - 1; s++) {
        load_stage(s, s * 32);
        asm volatile("cp.async.commit_group;\n");
    }
#pragma unroll 1
    for (int it = 0; it < NIT; it++) {
        int pre = it + ST - 1;
        if (pre < NIT) load_stage(pre & (ST - 1), pre * 32);
        asm volatile("cp.async.commit_group;\n");
        asm volatile("cp.async.wait_group %0;\n" :: "n"(ST - 1));
        __syncthreads();
        compute(it & (ST - 1));
        __syncthreads();
    }

    outproj_epilogue(acc, bias, C, (float*)dyn, n0, blockIdx.x, tid, wm, wn, g, t);
}

// ---------------- log_softmax finalize ---------------------------------------
#define NCHF 16
#define CHF  3142
__global__ void ls_final_kernel(float* __restrict__ out) {
    int b = blockIdx.x, c = blockIdx.y, t = threadIdx.x;
    __shared__ float sM[8], sS[8], lse_sh;

    float M = -INFINITY, S = 0.0f;
    for (int k = t; k < NB_OUT; k += 256) {
        float m2 = g_pmax[b * NB_OUT + k], s2 = g_psum[b * NB_OUT + k];
        if (m2 > M) { S = S * expf(M - m2) + s2; M = m2; }
        else        { S += s2 * expf(m2 - M); }
    }
#pragma unroll
    for (int o = 16; o; o >>= 1) {
        float m2 = __shfl_xor_sync(0xffffffffu, M, o);
        float s2 = __shfl_xor_sync(0xffffffffu, S, o);
        if (m2 > M) { S = S * expf(M - m2) + s2; M = m2; }
        else        { S += s2 * expf(m2 - M); }
    }
    if ((t & 31) == 0) { sM[t >> 5] = M; sS[t >> 5] = S; }
    __syncthreads();
    if (t == 0) {
        float Mg = sM[0], Sg = sS[0];
#pragma unroll
        for (int w = 1; w < 8; w++) {
            float m2 = sM[w], s2 = sS[w];
            if (m2 > Mg) { Sg = Sg * expf(Mg - m2) + s2; Mg = m2; }
            else         { Sg += s2 * expf(m2 - Mg); }
        }
        lse_sh = Mg + logf(Sg);
    }
    __syncthreads();
    float lse = lse_sh;

    int s0 = c * CHF, s1 = min(s0 + CHF, V);
    const float* row = &g_logits[(size_t)b * V];
    float* orow = &out[(size_t)b * V];
    int i = s0 + t;
    for (; i + 768 < s1; i += 1024) {
        float v0 = row[i], v1 = row[i + 256], v2 = row[i + 512], v3 = row[i + 768];
        orow[i]       = v0 - lse;
        orow[i + 256] = v1 - lse;
        orow[i + 512] = v2 - lse;
        orow[i + 768] = v3 - lse;
    }
    for (; i < s1; i += 256) orow[i] = row[i] - lse;
}

// ---------------- launcher ---------------------------------------------------
typedef CUresult (*EncodeFn)(CUtensorMap*, CUtensorMapDataType, cuuint32_t,
                             void*, const cuuint64_t*, const cuuint64_t*,
                             const cuuint32_t*, const cuuint32_t*,
                             CUtensorMapInterleave, CUtensorMapSwizzle,
                             CUtensorMapL2promotion, CUtensorMapFloatOOBfill);

extern "C" void kernel_launch(void* const* d_in, const int* in_sizes, int n_in,
                              void* d_out, int out_size) {
    const int*   input_tensor = (const int*)  d_in[0];
    const float* hidden       = (const float*)d_in[1];
    const float* enc          = (const float*)d_in[2];
    const float* emb_table    = (const float*)d_in[4];
    const float* attn_w       = (const float*)d_in[5];
    const float* attn_b       = (const float*)d_in[6];
    const float* comb_w       = (const float*)d_in[7];
    const float* comb_b       = (const float*)d_in[8];
    const float* w_ih         = (const float*)d_in[9];
    const float* w_hh         = (const float*)d_in[10];
    const float* b_ih         = (const float*)d_in[11];
    const float* b_hh         = (const float*)d_in[12];
    const float* out_w        = (const float*)d_in[13];
    const float* out_b        = (const float*)d_in[14];

    float* out        = (float*)d_out;
    float* out_logsm  = out;
    float* out_hnew   = out + (size_t)B * V;
    float* out_attn   = out + (size_t)B * V + (size_t)B * HD;

    float* d_attn_in; cudaGetSymbolAddress((void**)&d_attn_in, g_attn_in);
    float* d_comb_in; cudaGetSymbolAddress((void**)&d_comb_in, g_comb_in);
    float* d_logits;  cudaGetSymbolAddress((void**)&d_logits,  g_logits);
    float* d_x;       cudaGetSymbolAddress((void**)&d_x,       g_x);
    float* d_gi;      cudaGetSymbolAddress((void**)&d_gi,      g_gi);
    float* d_gh;      cudaGetSymbolAddress((void**)&d_gh,      g_gh);
    float* d_attn_lg; cudaGetSymbolAddress((void**)&d_attn_lg, g_attn_logits);

    static bool attr_set = false;
    if (!attr_set) {
        cudaFuncSetAttribute(out_proj_mma_kernel,
                             cudaFuncAttributeMaxDynamicSharedMemorySize, GEMM_SMEM);
        cudaFuncSetAttribute(out_proj_tma_kernel,
                             cudaFuncAttributeMaxDynamicSharedMemorySize, QSMEM);
        cudaFuncSetAttribute(gemm_tf32_kernel<false>,
                             cudaFuncAttributeMaxDynamicSharedMemorySize, TGEMM_SMEM);
        cudaFuncSetAttribute(gemm_tf32_kernel<true>,
                             cudaFuncAttributeMaxDynamicSharedMemorySize, TGEMM_SMEM);
        cudaFuncSetAttribute(gemm_pair_kernel,
                             cudaFuncAttributeMaxDynamicSharedMemorySize, TGEMM_SMEM);
        attr_set = true;
    }

    CUtensorMap tmap;
    bool use_tma = false;
    {
        void* h = dlopen("libcuda.so.1", RTLD_LAZY | RTLD_NOLOAD);
        if (!h) h = dlopen("libcuda.so.1", RTLD_LAZY);
        if (h) {
            EncodeFn fn = (EncodeFn)dlsym(h, "cuTensorMapEncodeTiled");
            if (fn) {
                cuuint64_t dims[2]    = {(cuuint64_t)HD, (cuuint64_t)V};
                cuuint64_t strides[1] = {(cuuint64_t)HD * sizeof(float)};
                cuuint32_t box[2]     = {32, 128};
                cuuint32_t estr[2]    = {1, 1};
                CUresult r = fn(&tmap, CU_TENSOR_MAP_DATA_TYPE_FLOAT32, 2,
                                (void*)out_w, dims, strides, box, estr,
                                CU_TENSOR_MAP_INTERLEAVE_NONE,
                                CU_TENSOR_MAP_SWIZZLE_128B,
                                CU_TENSOR_MAP_L2_PROMOTION_L2_128B,
                                CU_TENSOR_MAP_FLOAT_OOB_FILL_NONE);
                use_tma = (r == CUDA_SUCCESS);
            }
        }
    }

    // 1. embed + concat + bias/zero init (float4)
    prep_kernel<<<B + NBIAS4, 256>>>(input_tensor, hidden, emb_table,
                                     attn_b, comb_b, b_ih, b_hh);

    // 2. w_hh GEMM + attention-logits GEMM (one launch, 208 blocks)
    gemm_pair_kernel<<<208, 256, TGEMM_SMEM>>>(hidden, w_hh, d_gh,
                                               d_attn_in, attn_w, d_attn_lg);

    // 3. fused softmax + context
    context_fused_kernel<<<dim3(B, 8), 256>>>(enc, out_attn);

    // 4. comb GEMM (16 k-splits -> 128 blocks)
    gemm_tf32_kernel<false><<<dim3(HE / 128, 16), 256, TGEMM_SMEM>>>(
        d_comb_in, comb_w, d_x, HE, CAT, CAT / 16);

    // 5. GRU input GEMM (relu folded, 8 k-splits -> 192 blocks)
    gemm_tf32_kernel<true><<<dim3(G3 / 128, 8), 256, TGEMM_SMEM>>>(
        d_x, w_ih, d_gi, G3, HE, HE / 8);

    // 6. GRU elementwise
    gru_kernel<<<B, 256>>>(hidden, out_hnew);

    // 7. output projection + fused log-softmax partials
    if (use_tma) {
        out_proj_tma_kernel<<<NB_OUT, 256, QSMEM>>>(tmap, out_b, d_logits);
    } else {
        out_proj_mma_kernel<<<NB_OUT, 256, GEMM_SMEM>>>(out_w, out_b, d_logits);
    }

    // 8. log-softmax finalize
    ls_final_kernel<<<dim3(B, NCHF), 256>>>(out_logsm);
}